// round 7
// baseline (speedup 1.0000x reference)
#include <cuda_runtime.h>
#include <cuda_bf16.h>

#define T_STEPS 1000
#define NB 16
#define NI 440
#define NH 1024
#define NP 512
#define NG 4096          // 4 gates * NH
#define NCTA 128
#define RTHREADS 512

typedef unsigned long long ull;

// ---------------- device scratch (no allocations allowed) ----------------
__device__ float    g_gx[(size_t)T_STEPS * NG * NB];   // [t][gate_row][b]
__device__ float    g_U [(size_t)NG * NH];             // [gate_row][h_in]
__device__ float    g_hbuf[2][NB * NH];                // ping-pong h [b][h]
__device__ unsigned g_ctr;

// ---------------- helpers ----------------
__device__ __forceinline__ ull ffma2(ull a, ull b, ull c) {
    ull d;
    asm("fma.rn.f32x2 %0, %1, %2, %3;" : "=l"(d) : "l"(a), "l"(b), "l"(c));
    return d;
}
__device__ __forceinline__ void lds_v2u64(ull &a, ull &b, unsigned saddr) {
    asm volatile("ld.shared.v2.b64 {%0,%1}, [%2];" : "=l"(a), "=l"(b) : "r"(saddr));
}
__device__ __forceinline__ void ldg_cg_v2u64(ull &a, ull &b, const void *p) {
    asm volatile("ld.global.cg.v2.b64 {%0,%1}, [%2];" : "=l"(a), "=l"(b) : "l"(p));
}
__device__ __forceinline__ float sigf(float x) { return 1.0f / (1.0f + __expf(-x)); }

// ---------------- zero init (per launch) ----------------
__global__ void k_zero() {
    int i = blockIdx.x * 256 + threadIdx.x;
    if (i < NB * NH) g_hbuf[0][i] = 0.0f;
    if (i == 0) g_ctr = 0u;
}

// ---------------- U = T_g * wym  (M=1024, N=1024, K=512, z=gate) ----------------
__global__ __launch_bounds__(256) void k_gemm_U(
    const float* __restrict__ t0, const float* __restrict__ t1,
    const float* __restrict__ t2, const float* __restrict__ t3,
    const float* __restrict__ wym)
{
    __shared__ float As[8][128];   // [k][m]
    __shared__ float Bs[8][128];   // [k][n]
    const int g = blockIdx.z;
    const float* A = (g == 0) ? t0 : (g == 1) ? t1 : (g == 2) ? t2 : t3;  // [1024][512]
    const int m0 = blockIdx.y * 128;
    const int n0 = blockIdx.x * 128;
    const int tid = threadIdx.x;
    const int tn = tid & 15, tm = tid >> 4;
    const int lrow = tid >> 1, lk = (tid & 1) * 4;   // A loader
    const int krow = tid >> 5, ncol = (tid & 31) * 4; // B loader

    float acc[8][8];
#pragma unroll
    for (int i = 0; i < 8; i++)
#pragma unroll
        for (int j = 0; j < 8; j++) acc[i][j] = 0.0f;

    for (int k0 = 0; k0 < NP; k0 += 8) {
        float4 av = *(const float4*)(A + (size_t)(m0 + lrow) * NP + k0 + lk);
        float4 bv = *(const float4*)(wym + (size_t)(k0 + krow) * NH + n0 + ncol);
        __syncthreads();
        As[lk + 0][lrow] = av.x; As[lk + 1][lrow] = av.y;
        As[lk + 2][lrow] = av.z; As[lk + 3][lrow] = av.w;
        *(float4*)&Bs[krow][ncol] = bv;
        __syncthreads();
#pragma unroll
        for (int kk = 0; kk < 8; kk++) {
            float a[8], bb[8];
            *(float4*)(a)      = *(const float4*)&As[kk][tm * 8];
            *(float4*)(a + 4)  = *(const float4*)&As[kk][tm * 8 + 4];
            *(float4*)(bb)     = *(const float4*)&Bs[kk][tn * 8];
            *(float4*)(bb + 4) = *(const float4*)&Bs[kk][tn * 8 + 4];
#pragma unroll
            for (int i = 0; i < 8; i++)
#pragma unroll
                for (int j = 0; j < 8; j++) acc[i][j] += a[i] * bb[j];
        }
    }
#pragma unroll
    for (int i = 0; i < 8; i++) {
        float* dst = g_U + (size_t)(g * NH + m0 + tm * 8 + i) * NH + (n0 + tn * 8);
        *(float4*)(dst)     = make_float4(acc[i][0], acc[i][1], acc[i][2], acc[i][3]);
        *(float4*)(dst + 4) = make_float4(acc[i][4], acc[i][5], acc[i][6], acc[i][7]);
    }
}

// ---------------- gx = x @ W^T + b  (M=16000, N=4096, K=440) ----------------
// out: g_gx[t][n][b],  n = g*1024 + h,  m = t*16 + b
__global__ __launch_bounds__(256) void k_gemm_in(
    const float* __restrict__ x,
    const float* __restrict__ w0, const float* __restrict__ b0,
    const float* __restrict__ w1, const float* __restrict__ b1,
    const float* __restrict__ w2, const float* __restrict__ b2,
    const float* __restrict__ w3, const float* __restrict__ b3)
{
    __shared__ float As[8][128];   // [k][n] from W
    __shared__ float Bs[8][128];   // [k][m] from x
    const int nbx = blockIdx.x;    // 0..31
    const int mby = blockIdx.y;    // 0..124
    const int g = nbx >> 3;
    const float* W  = (g == 0) ? w0 : (g == 1) ? w1 : (g == 2) ? w2 : w3;
    const float* BV = (g == 0) ? b0 : (g == 1) ? b1 : (g == 2) ? b2 : b3;
    const int hbase = (nbx & 7) * 128;
    const int tid = threadIdx.x;
    const int tn = tid & 15, tm = tid >> 4;
    const int lrow = tid >> 1, lk = (tid & 1) * 4;

    float acc[8][8];
#pragma unroll
    for (int i = 0; i < 8; i++)
#pragma unroll
        for (int j = 0; j < 8; j++) acc[i][j] = 0.0f;

    for (int k0 = 0; k0 < NI; k0 += 8) {
        float4 av = *(const float4*)(W + (size_t)(hbase + lrow) * NI + k0 + lk);
        float4 bv = *(const float4*)(x + (size_t)(mby * 128 + lrow) * NI + k0 + lk);
        __syncthreads();
        As[lk + 0][lrow] = av.x; As[lk + 1][lrow] = av.y;
        As[lk + 2][lrow] = av.z; As[lk + 3][lrow] = av.w;
        Bs[lk + 0][lrow] = bv.x; Bs[lk + 1][lrow] = bv.y;
        Bs[lk + 2][lrow] = bv.z; Bs[lk + 3][lrow] = bv.w;
        __syncthreads();
#pragma unroll
        for (int kk = 0; kk < 8; kk++) {
            float a[8], bb[8];
            *(float4*)(a)      = *(const float4*)&As[kk][tn * 8];      // n dim
            *(float4*)(a + 4)  = *(const float4*)&As[kk][tn * 8 + 4];
            *(float4*)(bb)     = *(const float4*)&Bs[kk][tm * 8];      // m dim
            *(float4*)(bb + 4) = *(const float4*)&Bs[kk][tm * 8 + 4];
#pragma unroll
            for (int i = 0; i < 8; i++)
#pragma unroll
                for (int j = 0; j < 8; j++) acc[i][j] += a[i] * bb[j];
        }
    }

    const int m0 = mby * 128 + tm * 8;    // 8 consecutive m: same t, b = bb0..bb0+7
    const int tt = m0 >> 4;
    const int bb0 = m0 & 15;
#pragma unroll
    for (int i = 0; i < 8; i++) {
        const int h = hbase + tn * 8 + i;
        const int n = (g << 10) + h;
        const float bias = BV[h];
        float* dst = g_gx + ((size_t)tt * NG + n) * NB + bb0;
        *(float4*)(dst)     = make_float4(acc[i][0] + bias, acc[i][1] + bias,
                                          acc[i][2] + bias, acc[i][3] + bias);
        *(float4*)(dst + 4) = make_float4(acc[i][4] + bias, acc[i][5] + bias,
                                          acc[i][6] + bias, acc[i][7] + bias);
    }
}

// ---------------- persistent recurrence ----------------
// 128 CTAs * 512 threads. CTA c owns h-slice [c*8, c*8+8) across 4 gates (32 U rows).
// warp = 16 b x 2 ktiles(32k). Thread caches its 32-k h slice in regs; loops 32 rows
// with broadcast shared U loads + packed f32x2 FMA. SMEM tree reduces 16 warp partials.
__global__ void __launch_bounds__(RTHREADS, 1) k_rec(float* __restrict__ out)
{
    extern __shared__ float smem[];
    float* Us  = smem;                       // [32][1024]
    float* red = smem + 32 * 1024;           // [32*16][20]
    float* gv  = red + 32 * 16 * 20;         // [32][17]

    const int cblk = blockIdx.x;
    const int tid = threadIdx.x;
    const int w  = tid >> 5;
    const int l  = tid & 31;
    const int b  = l & 15;
    const int hi = l >> 4;                   // half-warp
    const int kt = (w << 1) | hi;            // ktile 0..31 (32 k each)
    const int hi4 = hi << 2;                 // chunk permutation (bank fix)

    // load this CTA's 32 U rows into SMEM
    for (int idx = tid; idx < 32 * 256; idx += RTHREADS) {
        const int r  = idx >> 8;
        const int kk = (idx & 255) << 2;
        const int n  = ((r >> 3) << 10) + cblk * 8 + (r & 7);
        *(float4*)&Us[r * 1024 + kk] = *(const float4*)&g_U[(size_t)n * 1024 + kk];
    }

    // reduction-phase ownership: one (row, b) per thread
    const int rr = tid >> 4;                 // 0..31
    const int rb = tid & 15;
    const int rn = ((rr >> 3) << 10) + cblk * 8 + (rr & 7);
    const size_t gx_off0 = (size_t)rn * NB + rb;

    unsigned usbase = (unsigned)__cvta_generic_to_shared(Us);
    const unsigned ubase_kt = usbase + (unsigned)(kt * 128);   // 32 floats * 4B

    // cell-phase ids (only tid<128 use them)
    const int cj  = tid >> 4;                // 0..7
    const int cbt = tid & 15;
    const int hg  = cblk * 8 + cj;
    float cstate = 0.0f;

    __syncthreads();

    for (int t = 0; t < T_STEPS; ++t) {
        const float* hcur = g_hbuf[t & 1];
        float*       hnxt = g_hbuf[(t + 1) & 1];

        // prefetch this thread's gx early (DRAM/L2 latency hidden under main loop)
        const float gxv = __ldcg(&g_gx[(size_t)t * (NG * NB) + gx_off0]);

        // load h slice (32 k) into registers, chunk-permuted per half-warp
        ull h2[16];
        const float* hp = hcur + b * 1024 + kt * 32;
#pragma unroll
        for (int j = 0; j < 8; ++j) {
            const int cidx = j ^ hi4;
            ldg_cg_v2u64(h2[2 * j], h2[2 * j + 1], hp + (cidx << 2));
        }

        ull acc[32];
#pragma unroll
        for (int r = 0; r < 32; ++r) acc[r] = 0ull;

#pragma unroll
        for (int r = 0; r < 32; ++r) {
            const unsigned ua = ubase_kt + (unsigned)(r * 4096);
#pragma unroll
            for (int j = 0; j < 8; ++j) {
                ull ux, uy;
                lds_v2u64(ux, uy, ua + (unsigned)((j ^ hi4) << 4));
                acc[r] = ffma2(ux, h2[2 * j],     acc[r]);
                acc[r] = ffma2(uy, h2[2 * j + 1], acc[r]);
            }
        }

        // intra-warp: fold f32x2 halves + the two ktiles (lane ^ 16)
#pragma unroll
        for (int r = 0; r < 32; ++r) {
            float lo, hi_f;
            asm("mov.b64 {%0,%1}, %2;" : "=f"(lo), "=f"(hi_f) : "l"(acc[r]));
            float s = lo + hi_f;
            s += __shfl_xor_sync(0xffffffffu, s, 16);
            if (hi == 0) red[(r * 16 + b) * 20 + w] = s;
        }
        __syncthreads();

        // cross-warp: sum 16 partials for (rr, rb)
        {
            const float* rp = &red[(rr * 16 + rb) * 20];
            float4 p0 = *(const float4*)(rp + 0);
            float4 p1 = *(const float4*)(rp + 4);
            float4 p2 = *(const float4*)(rp + 8);
            float4 p3 = *(const float4*)(rp + 12);
            float dot = ((p0.x + p0.y) + (p0.z + p0.w)) + ((p1.x + p1.y) + (p1.z + p1.w))
                      + ((p2.x + p2.y) + (p2.z + p2.w)) + ((p3.x + p3.y) + (p3.z + p3.w));
            gv[rr * 17 + rb] = gxv + dot;
        }
        __syncthreads();

        // cell update: rows f=0..7, i=8..15, o=16..23, c=24..31
        if (tid < 128) {
            const float fpre = gv[(cj)      * 17 + cbt];
            const float ipre = gv[(8 + cj)  * 17 + cbt];
            const float opre = gv[(16 + cj) * 17 + cbt];
            const float cpre = gv[(24 + cj) * 17 + cbt];
            const float it = sigf(ipre), ft = sigf(fpre), ot = sigf(opre);
            cstate = it * tanhf(cpre) + ft * cstate;
            const float hval = ot * tanhf(cstate);
            __stcg(&hnxt[cbt * NH + hg], hval);
            out[((size_t)t * NB + cbt) * NH + hg] = hval;
            __threadfence();
        }
        __syncthreads();

        // grid barrier: monotonic counter (reset each launch by k_zero)
        if (tid == 0) {
            atomicAdd(&g_ctr, 1u);
            const unsigned tgt = (unsigned)(t + 1) * NCTA;
            while (*((volatile unsigned*)&g_ctr) < tgt) { }
            __threadfence();
        }
        __syncthreads();
    }
}

#define REC_SMEM ((32 * 1024 + 32 * 16 * 20 + 32 * 17) * 4)

extern "C" void kernel_launch(void* const* d_in, const int* in_sizes, int n_in,
                              void* d_out, int out_size) {
    const float* x     = (const float*)d_in[0];
    const float* wfx_w = (const float*)d_in[1];
    const float* wfx_b = (const float*)d_in[2];
    const float* wix_w = (const float*)d_in[3];
    const float* wix_b = (const float*)d_in[4];
    const float* wox_w = (const float*)d_in[5];
    const float* wox_b = (const float*)d_in[6];
    const float* wcx_w = (const float*)d_in[7];
    const float* wcx_b = (const float*)d_in[8];
    const float* tfy_w = (const float*)d_in[9];
    const float* tiy_w = (const float*)d_in[10];
    const float* toy_w = (const float*)d_in[11];
    const float* tcy_w = (const float*)d_in[12];
    const float* wym_w = (const float*)d_in[13];
    float* out = (float*)d_out;

    cudaFuncSetAttribute(k_rec, cudaFuncAttributeMaxDynamicSharedMemorySize, REC_SMEM);

    k_zero<<<64, 256>>>();

    dim3 gU(8, 8, 4);
    k_gemm_U<<<gU, 256>>>(tfy_w, tiy_w, toy_w, tcy_w, wym_w);

    dim3 gI(32, 125);
    k_gemm_in<<<gI, 256>>>(x, wfx_w, wfx_b, wix_w, wix_b,
                           wox_w, wox_b, wcx_w, wcx_b);

    k_rec<<<NCTA, RTHREADS, REC_SMEM>>>(out);
}

// round 8
// speedup vs baseline: 1.0488x; 1.0488x over previous
#include <cuda_runtime.h>
#include <cuda_bf16.h>

#define T_STEPS 1000
#define NB 16
#define NI 440
#define NH 1024
#define NP 512
#define NG 4096          // 4 gates * NH
#define NCTA 128
#define RTHREADS 512

typedef unsigned long long ull;

// ---------------- device scratch (no allocations allowed) ----------------
__device__ float    g_gx[(size_t)T_STEPS * NG * NB];   // [t][gate_row][b]
__device__ float    g_U [(size_t)NG * NH];             // [gate_row][h_in]
__device__ float    g_hbuf[2][NB * NH];                // ping-pong h [b][h]
__device__ unsigned g_ctr;

// ---------------- helpers ----------------
__device__ __forceinline__ ull ffma2(ull a, ull b, ull c) {
    ull d;
    asm("fma.rn.f32x2 %0, %1, %2, %3;" : "=l"(d) : "l"(a), "l"(b), "l"(c));
    return d;
}
__device__ __forceinline__ ull pack2(float x, float y) {
    ull r;
    asm("mov.b64 %0, {%1,%2};" : "=l"(r) : "f"(x), "f"(y));
    return r;
}
__device__ __forceinline__ void unpack2(float &x, float &y, ull v) {
    asm("mov.b64 {%0,%1}, %2;" : "=f"(x), "=f"(y) : "l"(v));
}
__device__ __forceinline__ void lds_v2u64(ull &a, ull &b, unsigned saddr) {
    asm volatile("ld.shared.v2.b64 {%0,%1}, [%2];" : "=l"(a), "=l"(b) : "r"(saddr));
}
__device__ __forceinline__ void ldg_cg_v2u64(ull &a, ull &b, const void *p) {
    asm volatile("ld.global.cg.v2.b64 {%0,%1}, [%2];" : "=l"(a), "=l"(b) : "l"(p));
}
__device__ __forceinline__ float sigf(float x) { return 1.0f / (1.0f + __expf(-x)); }

// ---------------- zero init (per launch) ----------------
__global__ void k_zero() {
    int i = blockIdx.x * 256 + threadIdx.x;
    if (i < NB * NH) g_hbuf[0][i] = 0.0f;
    if (i == 0) g_ctr = 0u;
}

// ================= U = T_g * wym  (M=1024, N=1024, K=512, z=gate) =================
// f32x2 inner product, double-buffered smem, single sync per k-step.
__global__ __launch_bounds__(256, 2) void k_gemm_U(
    const float* __restrict__ t0, const float* __restrict__ t1,
    const float* __restrict__ t2, const float* __restrict__ t3,
    const float* __restrict__ wym)
{
    __shared__ float As[2][8][128];   // [k][m]  (m = gate_row dim)
    __shared__ float Bs[2][8][128];   // [k][n]  (n = h_in dim)
    const int g = blockIdx.z;
    const float* A = (g == 0) ? t0 : (g == 1) ? t1 : (g == 2) ? t2 : t3;  // [1024][512]
    const int m0 = blockIdx.y * 128;
    const int n0 = blockIdx.x * 128;
    const int tid = threadIdx.x;
    const int tn = tid & 15, tm = tid >> 4;           // tn->n pairs, tm->m
    const int lrow = tid >> 1, lk = (tid & 1) * 4;    // A loader (transpose)
    const int krow = tid >> 5, ncol = (tid & 31) * 4; // B loader (direct)

    ull acc[8][4];                                    // [m][n-pair]
#pragma unroll
    for (int i = 0; i < 8; i++)
#pragma unroll
        for (int j = 0; j < 4; j++) acc[i][j] = 0ull;

    // preload k-step 0
    {
        float4 av = *(const float4*)(A + (size_t)(m0 + lrow) * NP + lk);
        float4 bv = *(const float4*)(wym + (size_t)(krow) * NH + n0 + ncol);
        As[0][lk + 0][lrow] = av.x; As[0][lk + 1][lrow] = av.y;
        As[0][lk + 2][lrow] = av.z; As[0][lk + 3][lrow] = av.w;
        *(float4*)&Bs[0][krow][ncol] = bv;
    }
    __syncthreads();

    const int NIT = NP / 8;   // 64
    for (int it = 0; it < NIT; ++it) {
        const int cur = it & 1, nxt = cur ^ 1;
        float4 av, bv;
        if (it + 1 < NIT) {
            const int k0 = (it + 1) * 8;
            av = *(const float4*)(A + (size_t)(m0 + lrow) * NP + k0 + lk);
            bv = *(const float4*)(wym + (size_t)(k0 + krow) * NH + n0 + ncol);
        }
#pragma unroll
        for (int kk = 0; kk < 8; kk++) {
            float a[8];
            *(float4*)(a)     = *(const float4*)&As[cur][kk][tm * 8];
            *(float4*)(a + 4) = *(const float4*)&As[cur][kk][tm * 8 + 4];
            float4 b0 = *(const float4*)&Bs[cur][kk][tn * 8];
            float4 b1 = *(const float4*)&Bs[cur][kk][tn * 8 + 4];
            ull bq[4] = { pack2(b0.x, b0.y), pack2(b0.z, b0.w),
                          pack2(b1.x, b1.y), pack2(b1.z, b1.w) };
#pragma unroll
            for (int i = 0; i < 8; i++) {
                ull as = pack2(a[i], a[i]);
#pragma unroll
                for (int j = 0; j < 4; j++) acc[i][j] = ffma2(as, bq[j], acc[i][j]);
            }
        }
        if (it + 1 < NIT) {
            As[nxt][lk + 0][lrow] = av.x; As[nxt][lk + 1][lrow] = av.y;
            As[nxt][lk + 2][lrow] = av.z; As[nxt][lk + 3][lrow] = av.w;
            *(float4*)&Bs[nxt][krow][ncol] = bv;
        }
        __syncthreads();
    }

#pragma unroll
    for (int i = 0; i < 8; i++) {
        float v[8];
#pragma unroll
        for (int j = 0; j < 4; j++) unpack2(v[2 * j], v[2 * j + 1], acc[i][j]);
        float* dst = g_U + (size_t)(g * NH + m0 + tm * 8 + i) * NH + (n0 + tn * 8);
        *(float4*)(dst)     = make_float4(v[0], v[1], v[2], v[3]);
        *(float4*)(dst + 4) = make_float4(v[4], v[5], v[6], v[7]);
    }
}

// ================= gx = x @ W^T + b  (M=16000, N=4096, K=440) =================
// out: g_gx[t][n][b],  n = g*1024 + h,  m = t*16 + b
__global__ __launch_bounds__(256, 2) void k_gemm_in(
    const float* __restrict__ x,
    const float* __restrict__ w0, const float* __restrict__ b0,
    const float* __restrict__ w1, const float* __restrict__ b1,
    const float* __restrict__ w2, const float* __restrict__ b2,
    const float* __restrict__ w3, const float* __restrict__ b3)
{
    __shared__ float As[2][8][128];   // [k][n] from W
    __shared__ float Bs[2][8][128];   // [k][m] from x
    const int nbx = blockIdx.x;       // 0..31
    const int mby = blockIdx.y;       // 0..124
    const int g = nbx >> 3;
    const float* W  = (g == 0) ? w0 : (g == 1) ? w1 : (g == 2) ? w2 : w3;
    const float* BV = (g == 0) ? b0 : (g == 1) ? b1 : (g == 2) ? b2 : b3;
    const int hbase = (nbx & 7) * 128;
    const int tid = threadIdx.x;
    const int tn = tid & 15, tm = tid >> 4;        // tn->n, tm->m pairs
    const int lrow = tid >> 1, lk = (tid & 1) * 4;

    ull acc[8][4];                                 // [n][m-pair]
#pragma unroll
    for (int i = 0; i < 8; i++)
#pragma unroll
        for (int j = 0; j < 4; j++) acc[i][j] = 0ull;

    {
        float4 av = *(const float4*)(W + (size_t)(hbase + lrow) * NI + lk);
        float4 bv = *(const float4*)(x + (size_t)(mby * 128 + lrow) * NI + lk);
        As[0][lk + 0][lrow] = av.x; As[0][lk + 1][lrow] = av.y;
        As[0][lk + 2][lrow] = av.z; As[0][lk + 3][lrow] = av.w;
        Bs[0][lk + 0][lrow] = bv.x; Bs[0][lk + 1][lrow] = bv.y;
        Bs[0][lk + 2][lrow] = bv.z; Bs[0][lk + 3][lrow] = bv.w;
    }
    __syncthreads();

    const int NIT = NI / 8;   // 55
    for (int it = 0; it < NIT; ++it) {
        const int cur = it & 1, nxt = cur ^ 1;
        float4 av, bv;
        if (it + 1 < NIT) {
            const int k0 = (it + 1) * 8;
            av = *(const float4*)(W + (size_t)(hbase + lrow) * NI + k0 + lk);
            bv = *(const float4*)(x + (size_t)(mby * 128 + lrow) * NI + k0 + lk);
        }
#pragma unroll
        for (int kk = 0; kk < 8; kk++) {
            float a[8];
            *(float4*)(a)     = *(const float4*)&As[cur][kk][tn * 8];   // n dim
            *(float4*)(a + 4) = *(const float4*)&As[cur][kk][tn * 8 + 4];
            float4 m0v = *(const float4*)&Bs[cur][kk][tm * 8];          // m dim
            float4 m1v = *(const float4*)&Bs[cur][kk][tm * 8 + 4];
            ull bq[4] = { pack2(m0v.x, m0v.y), pack2(m0v.z, m0v.w),
                          pack2(m1v.x, m1v.y), pack2(m1v.z, m1v.w) };
#pragma unroll
            for (int i = 0; i < 8; i++) {
                ull as = pack2(a[i], a[i]);
#pragma unroll
                for (int j = 0; j < 4; j++) acc[i][j] = ffma2(as, bq[j], acc[i][j]);
            }
        }
        if (it + 1 < NIT) {
            As[nxt][lk + 0][lrow] = av.x; As[nxt][lk + 1][lrow] = av.y;
            As[nxt][lk + 2][lrow] = av.z; As[nxt][lk + 3][lrow] = av.w;
            Bs[nxt][lk + 0][lrow] = bv.x; Bs[nxt][lk + 1][lrow] = bv.y;
            Bs[nxt][lk + 2][lrow] = bv.z; Bs[nxt][lk + 3][lrow] = bv.w;
        }
        __syncthreads();
    }

    const int m0 = mby * 128 + tm * 8;    // 8 consecutive m: same t, b = bb0..bb0+7
    const int tt = m0 >> 4;
    const int bb0 = m0 & 15;
#pragma unroll
    for (int i = 0; i < 8; i++) {
        const int h = hbase + tn * 8 + i;
        const int n = (g << 10) + h;
        const float bias = BV[h];
        float v[8];
#pragma unroll
        for (int j = 0; j < 4; j++) unpack2(v[2 * j], v[2 * j + 1], acc[i][j]);
        float* dst = g_gx + ((size_t)tt * NG + n) * NB + bb0;
        *(float4*)(dst)     = make_float4(v[0] + bias, v[1] + bias,
                                          v[2] + bias, v[3] + bias);
        *(float4*)(dst + 4) = make_float4(v[4] + bias, v[5] + bias,
                                          v[6] + bias, v[7] + bias);
    }
}

// ================= persistent recurrence =================
// 128 CTAs * 512 threads. CTA c owns h-slice [c*8, c*8+8) across 4 gates (32 U rows).
// warp = 16 b x 2 ktiles(32k). Thread caches its 32-k h slice in regs.
// j-outer / r-inner: acc[r] reuse is ~96 instructions apart -> no RAW stalls,
// LDS latency hidden by the 31 other rows in flight.
__global__ void __launch_bounds__(RTHREADS, 1) k_rec(float* __restrict__ out)
{
    extern __shared__ float smem[];
    float* Us  = smem;                       // [32][1024]
    float* red = smem + 32 * 1024;           // [32*16][20]
    float* gv  = red + 32 * 16 * 20;         // [32][17]

    const int cblk = blockIdx.x;
    const int tid = threadIdx.x;
    const int w  = tid >> 5;
    const int l  = tid & 31;
    const int b  = l & 15;
    const int hi = l >> 4;                   // half-warp
    const int kt = (w << 1) | hi;            // ktile 0..31 (32 k each)
    const int hi4 = hi << 2;                 // chunk permutation (bank fix)

    // load this CTA's 32 U rows into SMEM
    for (int idx = tid; idx < 32 * 256; idx += RTHREADS) {
        const int r  = idx >> 8;
        const int kk = (idx & 255) << 2;
        const int n  = ((r >> 3) << 10) + cblk * 8 + (r & 7);
        *(float4*)&Us[r * 1024 + kk] = *(const float4*)&g_U[(size_t)n * 1024 + kk];
    }

    // reduction-phase ownership: one (row, b) per thread
    const int rr = tid >> 4;                 // 0..31
    const int rb = tid & 15;
    const int rn = ((rr >> 3) << 10) + cblk * 8 + (rr & 7);
    const size_t gx_off0 = (size_t)rn * NB + rb;

    unsigned usbase = (unsigned)__cvta_generic_to_shared(Us);
    const unsigned ubase_kt = usbase + (unsigned)(kt * 128);   // 32 floats * 4B

    // cell-phase ids (only tid<128 use them)
    const int cj  = tid >> 4;                // 0..7
    const int cbt = tid & 15;
    const int hg  = cblk * 8 + cj;
    float cstate = 0.0f;

    __syncthreads();

    for (int t = 0; t < T_STEPS; ++t) {
        const float* hcur = g_hbuf[t & 1];
        float*       hnxt = g_hbuf[(t + 1) & 1];

        // prefetch this thread's gx early (L2 latency hidden under main loop)
        const float gxv = __ldcg(&g_gx[(size_t)t * (NG * NB) + gx_off0]);

        // load h slice (32 k) into registers, chunk-permuted per half-warp
        ull h2[16];
        const float* hp = hcur + b * 1024 + kt * 32;
#pragma unroll
        for (int j = 0; j < 8; ++j) {
            const int cidx = j ^ hi4;
            ldg_cg_v2u64(h2[2 * j], h2[2 * j + 1], hp + (cidx << 2));
        }

        ull acc[32];
#pragma unroll
        for (int r = 0; r < 32; ++r) acc[r] = 0ull;

#pragma unroll
        for (int j = 0; j < 8; ++j) {
            const ull hx = h2[2 * j];
            const ull hy = h2[2 * j + 1];
            const unsigned joff = (unsigned)((j ^ hi4) << 4);
#pragma unroll
            for (int r = 0; r < 32; ++r) {
                ull ux, uy;
                lds_v2u64(ux, uy, ubase_kt + (unsigned)(r * 4096) + joff);
                acc[r] = ffma2(ux, hx, acc[r]);
                acc[r] = ffma2(uy, hy, acc[r]);
            }
        }

        // intra-warp: fold f32x2 halves + the two ktiles (lane ^ 16)
#pragma unroll
        for (int r = 0; r < 32; ++r) {
            float lo, hi_f;
            unpack2(lo, hi_f, acc[r]);
            float s = lo + hi_f;
            s += __shfl_xor_sync(0xffffffffu, s, 16);
            if (hi == 0) red[(r * 16 + b) * 20 + w] = s;
        }
        __syncthreads();

        // cross-warp: sum 16 partials for (rr, rb)
        {
            const float* rp = &red[(rr * 16 + rb) * 20];
            float4 p0 = *(const float4*)(rp + 0);
            float4 p1 = *(const float4*)(rp + 4);
            float4 p2 = *(const float4*)(rp + 8);
            float4 p3 = *(const float4*)(rp + 12);
            float dot = ((p0.x + p0.y) + (p0.z + p0.w)) + ((p1.x + p1.y) + (p1.z + p1.w))
                      + ((p2.x + p2.y) + (p2.z + p2.w)) + ((p3.x + p3.y) + (p3.z + p3.w));
            gv[rr * 17 + rb] = gxv + dot;
        }
        __syncthreads();

        // cell update: rows f=0..7, i=8..15, o=16..23, c=24..31
        if (tid < 128) {
            const float fpre = gv[(cj)      * 17 + cbt];
            const float ipre = gv[(8 + cj)  * 17 + cbt];
            const float opre = gv[(16 + cj) * 17 + cbt];
            const float cpre = gv[(24 + cj) * 17 + cbt];
            const float it = sigf(ipre), ft = sigf(fpre), ot = sigf(opre);
            cstate = it * tanhf(cpre) + ft * cstate;
            const float hval = ot * tanhf(cstate);
            __stcg(&hnxt[cbt * NH + hg], hval);
            out[((size_t)t * NB + cbt) * NH + hg] = hval;
        }
        __syncthreads();

        // grid barrier: monotonic counter (reset each launch by k_zero)
        if (tid == 0) {
            __threadfence();                 // release: h stores -> counter
            atomicAdd(&g_ctr, 1u);
            const unsigned tgt = (unsigned)(t + 1) * NCTA;
            while (*((volatile unsigned*)&g_ctr) < tgt) { }
            __threadfence();                 // acquire: counter -> next h loads
        }
        __syncthreads();
    }
}

#define REC_SMEM ((32 * 1024 + 32 * 16 * 20 + 32 * 17) * 4)

extern "C" void kernel_launch(void* const* d_in, const int* in_sizes, int n_in,
                              void* d_out, int out_size) {
    const float* x     = (const float*)d_in[0];
    const float* wfx_w = (const float*)d_in[1];
    const float* wfx_b = (const float*)d_in[2];
    const float* wix_w = (const float*)d_in[3];
    const float* wix_b = (const float*)d_in[4];
    const float* wox_w = (const float*)d_in[5];
    const float* wox_b = (const float*)d_in[6];
    const float* wcx_w = (const float*)d_in[7];
    const float* wcx_b = (const float*)d_in[8];
    const float* tfy_w = (const float*)d_in[9];
    const float* tiy_w = (const float*)d_in[10];
    const float* toy_w = (const float*)d_in[11];
    const float* tcy_w = (const float*)d_in[12];
    const float* wym_w = (const float*)d_in[13];
    float* out = (float*)d_out;

    cudaFuncSetAttribute(k_rec, cudaFuncAttributeMaxDynamicSharedMemorySize, REC_SMEM);

    k_zero<<<64, 256>>>();

    dim3 gU(8, 8, 4);
    k_gemm_U<<<gU, 256>>>(tfy_w, tiy_w, toy_w, tcy_w, wym_w);

    dim3 gI(32, 125);
    k_gemm_in<<<gI, 256>>>(x, wfx_w, wfx_b, wix_w, wix_b,
                           wox_w, wox_b, wcx_w, wcx_b);

    k_rec<<<NCTA, RTHREADS, REC_SMEM>>>(out);
}